// round 8
// baseline (speedup 1.0000x reference)
#include <cuda_runtime.h>
#include <math.h>

// ---------------- problem dims (fixed) ----------------
#define NN 50000
#define EE 600000
#define FIN 128
#define HID 128
#define KH 8
#define DA 16
#define DV 16
#define DM 64
#define NCLS 40
#define WO_IN  (HID + KH*DV)       // 256
#define QS2 464                    // q(128)|k(128)|v(128)|m(64)|gx(8)|gm(8)
#define SLOPE 0.1f

// ---------------- device scratch (no allocations allowed) ----------------
__device__ float g_h    [NN*HID];
__device__ float g_h2   [NN*HID];
__device__ float g_qkvm [(size_t)NN*QS2];
__device__ float g_wqkvm[HID*QS2];
__device__ float g_woin [NN*WO_IN];
__device__ float g_logits[NN*NCLS];
__device__ int   g_cnt   [NN];
__device__ int   g_rowptr[NN+1];
__device__ int   g_wptr  [NN];
__device__ int   g_esrc  [EE];

// ---------------- f32x2 packed helpers ----------------
__device__ __forceinline__ unsigned long long fma2(unsigned long long a,
                                                   unsigned long long b,
                                                   unsigned long long c) {
    unsigned long long d;
    asm("fma.rn.f32x2 %0, %1, %2, %3;" : "=l"(d) : "l"(a), "l"(b), "l"(c));
    return d;
}
__device__ __forceinline__ unsigned long long dup2(float x) {
    unsigned long long d;
    asm("mov.b64 %0, {%1, %1};" : "=l"(d) : "f"(x));
    return d;
}
__device__ __forceinline__ void unpk2(unsigned long long d, float& lo, float& hi) {
    asm("mov.b64 {%0, %1}, %2;" : "=f"(lo), "=f"(hi) : "l"(d));
}

// ---------------- CSR build ----------------
__global__ void zero_cnt_k(int* cnt) {
    int i = blockIdx.x * blockDim.x + threadIdx.x;
    if (i < NN) cnt[i] = 0;
}
__global__ void hist_k(const int* __restrict__ dst, int* __restrict__ cnt) {
    int e = blockIdx.x * blockDim.x + threadIdx.x;
    if (e < EE) atomicAdd(&cnt[dst[e]], 1);
}
__global__ void scan_k(const int* __restrict__ cnt, int* __restrict__ rowptr,
                       int* __restrict__ wptr) {
    __shared__ int ps[1024];
    const int C = (NN + 1023) / 1024;
    int t = threadIdx.x;
    int base = t * C;
    int sum = 0;
    for (int j = 0; j < C; j++) {
        int idx = base + j;
        if (idx < NN) sum += cnt[idx];
    }
    ps[t] = sum; __syncthreads();
    for (int off = 1; off < 1024; off <<= 1) {
        int v = (t >= off) ? ps[t - off] : 0;
        __syncthreads();
        ps[t] += v;
        __syncthreads();
    }
    int running = ps[t] - sum;
    if (t == 0) rowptr[0] = 0;
    for (int j = 0; j < C; j++) {
        int idx = base + j;
        if (idx < NN) {
            wptr[idx] = running;
            running += cnt[idx];
            rowptr[idx + 1] = running;
        }
    }
}
__global__ void scatter_k(const int* __restrict__ src, const int* __restrict__ dst,
                          int* __restrict__ wptr, int* __restrict__ esrc) {
    int e = blockIdx.x * blockDim.x + threadIdx.x;
    if (e < EE) {
        int pos = atomicAdd(&wptr[dst[e]], 1);
        esrc[pos] = src[e];
    }
}

// pack layer weights [128 x 464] = [Wq | Wk | Wv | Wm | Wg_x | Wg_mean]
__global__ void pack_qkvm_k(const float* __restrict__ Wq, const float* __restrict__ Wk,
                            const float* __restrict__ Wv, const float* __restrict__ Wm,
                            const float* __restrict__ Wg, float* __restrict__ Bf) {
    int idx = blockIdx.x * blockDim.x + threadIdx.x;
    if (idx >= HID*QS2) return;
    int r = idx / QS2, c = idx % QS2;
    float v;
    if      (c < 128) v = Wq[r*128 + c];
    else if (c < 256) v = Wk[r*128 + (c-128)];
    else if (c < 384) v = Wv[r*128 + (c-256)];
    else if (c < 448) v = Wm[r*64  + (c-384)];
    else if (c < 456) v = Wg[r*KH + (c-448)];            // x rows of Wg
    else              v = Wg[(192 + r)*KH + (c-456)];    // mean rows of Wg
    Bf[idx] = v;
}

// ---------------- 128x128x16 SGEMM, 8x8 microtile, f32x2, double-buffered ----
// Requires: Kc % 16 == 0, Nc % 4 == 0.
__global__ __launch_bounds__(256, 2)
void sgemm128_k(const float* __restrict__ A, const float* __restrict__ B,
                float* __restrict__ C, int M, int Nc, int Kc, int act) {
    __shared__ float As[2][16][128];
    __shared__ float Bs[2][16][128];
    int tid = threadIdx.x;
    int tx = tid & 15, ty = tid >> 4;
    int rowBase = blockIdx.y * 128;
    int colBase = blockIdx.x * 128;

    int arow  = tid >> 1;
    int acol4 = (tid & 1) * 4;
    int brow  = tid >> 5;
    int bcol4 = (tid & 31) * 4;
    int agr = rowBase + arow;
    int bgc = colBase + bcol4;

    float4 pa[2], pb[2];

    #pragma unroll
    for (int half = 0; half < 2; half++) {
        int ac = acol4 + half * 8;
        pa[half] = make_float4(0.f, 0.f, 0.f, 0.f);
        if (agr < M) pa[half] = *(const float4*)(A + (size_t)agr*Kc + ac);
        pb[half] = make_float4(0.f, 0.f, 0.f, 0.f);
        if (bgc < Nc) pb[half] = *(const float4*)(B + (size_t)(brow + half*8)*Nc + bgc);
    }
    #pragma unroll
    for (int half = 0; half < 2; half++) {
        int ac = acol4 + half * 8;
        As[0][ac+0][arow] = pa[half].x;
        As[0][ac+1][arow] = pa[half].y;
        As[0][ac+2][arow] = pa[half].z;
        As[0][ac+3][arow] = pa[half].w;
        *(float4*)&Bs[0][brow + half*8][bcol4] = pb[half];
    }
    __syncthreads();

    unsigned long long acc2[8][4];
    #pragma unroll
    for (int i = 0; i < 8; i++)
        #pragma unroll
        for (int j = 0; j < 4; j++) acc2[i][j] = 0ull;

    int nchunks = Kc >> 4;
    for (int c = 0; c < nchunks; c++) {
        int cur = c & 1;
        if (c + 1 < nchunks) {
            int k0 = (c + 1) << 4;
            #pragma unroll
            for (int half = 0; half < 2; half++) {
                int ac = acol4 + half * 8;
                pa[half] = make_float4(0.f, 0.f, 0.f, 0.f);
                if (agr < M) pa[half] = *(const float4*)(A + (size_t)agr*Kc + k0 + ac);
                pb[half] = make_float4(0.f, 0.f, 0.f, 0.f);
                if (bgc < Nc) pb[half] = *(const float4*)(B + (size_t)(k0 + brow + half*8)*Nc + bgc);
            }
        }
        #pragma unroll
        for (int kk = 0; kk < 16; kk++) {
            float4 a0 = *(const float4*)&As[cur][kk][ty*4];
            float4 a1 = *(const float4*)&As[cur][kk][64 + ty*4];
            const unsigned long long* bp0 = (const unsigned long long*)&Bs[cur][kk][tx*4];
            const unsigned long long* bp1 = (const unsigned long long*)&Bs[cur][kk][64 + tx*4];
            unsigned long long b2[4] = {bp0[0], bp0[1], bp1[0], bp1[1]};
            float a[8] = {a0.x,a0.y,a0.z,a0.w, a1.x,a1.y,a1.z,a1.w};
            #pragma unroll
            for (int i = 0; i < 8; i++) {
                unsigned long long ad = dup2(a[i]);
                acc2[i][0] = fma2(ad, b2[0], acc2[i][0]);
                acc2[i][1] = fma2(ad, b2[1], acc2[i][1]);
                acc2[i][2] = fma2(ad, b2[2], acc2[i][2]);
                acc2[i][3] = fma2(ad, b2[3], acc2[i][3]);
            }
        }
        if (c + 1 < nchunks) {
            int nxt = cur ^ 1;
            #pragma unroll
            for (int half = 0; half < 2; half++) {
                int ac = acol4 + half * 8;
                As[nxt][ac+0][arow] = pa[half].x;
                As[nxt][ac+1][arow] = pa[half].y;
                As[nxt][ac+2][arow] = pa[half].z;
                As[nxt][ac+3][arow] = pa[half].w;
                *(float4*)&Bs[nxt][brow + half*8][bcol4] = pb[half];
            }
        }
        __syncthreads();
    }

    #pragma unroll
    for (int ih = 0; ih < 2; ih++) {
        #pragma unroll
        for (int i = 0; i < 4; i++) {
            int gr = rowBase + ih*64 + ty*4 + i;
            if (gr >= M) continue;
            #pragma unroll
            for (int jh = 0; jh < 2; jh++) {
                int gc = colBase + jh*64 + tx*4;
                if (gc >= Nc) continue;
                float4 vv;
                unpk2(acc2[ih*4+i][jh*2+0], vv.x, vv.y);
                unpk2(acc2[ih*4+i][jh*2+1], vv.z, vv.w);
                if (act == 1) {
                    vv.x = vv.x > 0.f ? vv.x : SLOPE*vv.x;
                    vv.y = vv.y > 0.f ? vv.y : SLOPE*vv.y;
                    vv.z = vv.z > 0.f ? vv.z : SLOPE*vv.z;
                    vv.w = vv.w > 0.f ? vv.w : SLOPE*vv.w;
                }
                *(float4*)(C + (size_t)gr*Nc + gc) = vv;
            }
        }
    }
}

// ---------------- fused node kernel: attn+pool+gate+woin ----------------
// warp per node; online softmax; 2-way edge unroll for MLP.
__global__ __launch_bounds__(256)
void node_fused_k(const float* __restrict__ qkvm, const float* __restrict__ h,
                  const int* __restrict__ rowptr, const int* __restrict__ esrc,
                  const float* __restrict__ Wg, float* __restrict__ woin) {
    __shared__ float Ws[DM][KH+1];        // maxpool rows of Wg (64x8), padded
    int tid = threadIdx.x;                // 256
    for (int i = tid; i < DM*KH; i += 256) Ws[i/KH][i%KH] = Wg[(128 + i/KH)*KH + (i%KH)];
    __syncthreads();

    int warp = tid >> 5, lane = tid & 31;
    int n = blockIdx.x * 8 + warp;
    if (n >= NN) return;
    int head = lane >> 2;

    float4 q4 = *(const float4*)(qkvm + (size_t)n*QS2 + lane*4);   // q
    int start = rowptr[n], end = rowptr[n+1];
    int cnt = end - start;

    // two independent accumulator sets (even/odd edges)
    float smxA = -INFINITY, denA = 0.f;
    float smxB = -INFINITY, denB = 0.f;
    float4 accA = make_float4(0.f, 0.f, 0.f, 0.f);
    float4 accB = make_float4(0.f, 0.f, 0.f, 0.f);
    float mx0A = -INFINITY, mx1A = -INFINITY, gmA = 0.f;
    float mx0B = -INFINITY, mx1B = -INFINITY, gmB = 0.f;

    int i = start;
    for (; i + 1 < end; i += 2) {
        int sA = esrc[i], sB = esrc[i+1];
        const float* bA = qkvm + (size_t)sA*QS2;
        const float* bB = qkvm + (size_t)sB*QS2;
        float4 kA = *(const float4*)(bA + 128 + lane*4);
        float4 kB = *(const float4*)(bB + 128 + lane*4);
        float4 vA = *(const float4*)(bA + 256 + lane*4);
        float4 vB = *(const float4*)(bB + 256 + lane*4);
        float mA0 = bA[384 + lane], mA1 = bA[416 + lane], gA = bA[456 + head];
        float mB0 = bB[384 + lane], mB1 = bB[416 + lane], gB = bB[456 + head];

        float pA = q4.x*kA.x + q4.y*kA.y + q4.z*kA.z + q4.w*kA.w;
        float pB = q4.x*kB.x + q4.y*kB.y + q4.z*kB.z + q4.w*kB.w;
        pA += __shfl_xor_sync(0xffffffffu, pA, 1);
        pB += __shfl_xor_sync(0xffffffffu, pB, 1);
        pA += __shfl_xor_sync(0xffffffffu, pA, 2);
        pB += __shfl_xor_sync(0xffffffffu, pB, 2);

        float nmA = fmaxf(smxA, pA);
        float nmB = fmaxf(smxB, pB);
        float scA = __expf(smxA - nmA), exA = __expf(pA - nmA);
        float scB = __expf(smxB - nmB), exB = __expf(pB - nmB);
        denA = denA*scA + exA;
        denB = denB*scB + exB;
        accA.x = accA.x*scA + exA*vA.x; accA.y = accA.y*scA + exA*vA.y;
        accA.z = accA.z*scA + exA*vA.z; accA.w = accA.w*scA + exA*vA.w;
        accB.x = accB.x*scB + exB*vB.x; accB.y = accB.y*scB + exB*vB.y;
        accB.z = accB.z*scB + exB*vB.z; accB.w = accB.w*scB + exB*vB.w;
        smxA = nmA; smxB = nmB;
        mx0A = fmaxf(mx0A, mA0); mx1A = fmaxf(mx1A, mA1); gmA += gA;
        mx0B = fmaxf(mx0B, mB0); mx1B = fmaxf(mx1B, mB1); gmB += gB;
    }
    if (i < end) {
        int s = esrc[i];
        const float* base = qkvm + (size_t)s*QS2;
        float4 k4 = *(const float4*)(base + 128 + lane*4);
        float4 v4 = *(const float4*)(base + 256 + lane*4);
        float p = q4.x*k4.x + q4.y*k4.y + q4.z*k4.z + q4.w*k4.w;
        p += __shfl_xor_sync(0xffffffffu, p, 1);
        p += __shfl_xor_sync(0xffffffffu, p, 2);
        float nm = fmaxf(smxA, p);
        float sc = __expf(smxA - nm), ex = __expf(p - nm);
        denA = denA*sc + ex;
        accA.x = accA.x*sc + ex*v4.x; accA.y = accA.y*sc + ex*v4.y;
        accA.z = accA.z*sc + ex*v4.z; accA.w = accA.w*sc + ex*v4.w;
        smxA = nm;
        mx0A = fmaxf(mx0A, base[384 + lane]);
        mx1A = fmaxf(mx1A, base[416 + lane]);
        gmA += base[456 + head];
    }

    // merge A/B
    float smx = fmaxf(smxA, smxB);
    float wA = __expf(smxA - smx), wB = __expf(smxB - smx);   // exp(-inf)=0 safe
    float denom = denA*wA + denB*wB;
    float4 acc;
    acc.x = accA.x*wA + accB.x*wB;
    acc.y = accA.y*wA + accB.y*wB;
    acc.z = accA.z*wA + accB.z*wB;
    acc.w = accA.w*wA + accB.w*wB;
    float mx0 = fmaxf(mx0A, mx0B), mx1 = fmaxf(mx1A, mx1B);
    float gmsum = gmA + gmB;

    float inv = 1.f / (denom + 1e-16f);
    float4 o = make_float4(acc.x*inv, acc.y*inv, acc.z*inv, acc.w*inv);  // agg

    float mp0 = cnt ? mx0 : 0.f, mp1 = cnt ? mx1 : 0.f;
    float invd = 1.f / fmaxf((float)cnt, 1.f);

    // gate FC over maxpool (64 dims spread over lanes)
    float ga[KH] = {};
    #pragma unroll
    for (int oo = 0; oo < KH; oo++)
        ga[oo] = mp0 * Ws[lane][oo] + mp1 * Ws[lane + 32][oo];
    #pragma unroll
    for (int oo = 0; oo < KH; oo++)
        #pragma unroll
        for (int off = 16; off; off >>= 1)
            ga[oo] += __shfl_xor_sync(0xffffffffu, ga[oo], off);

    float gsum = ga[0];
    #pragma unroll
    for (int oo = 1; oo < KH; oo++) if (head == oo) gsum = ga[oo];
    gsum += qkvm[(size_t)n*QS2 + 448 + head];    // x part of gate
    gsum += gmsum * invd;                        // mean part of gate
    float gh = 1.f / (1.f + expf(-gsum));

    // write woin row: [h | g*agg]
    const float* hn = h + (size_t)n*HID;
    float* w = woin + (size_t)n*WO_IN;
    *(float4*)(w + lane*4) = *(const float4*)(hn + lane*4);
    *(float4*)(w + 128 + lane*4) = make_float4(gh*o.x, gh*o.y, gh*o.z, gh*o.w);
}

// row-wise log_softmax over 40 classes; one warp per row
__global__ void logsoftmax_k(const float* __restrict__ logits, float* __restrict__ out) {
    int row = blockIdx.x * 4 + (threadIdx.x >> 5);
    int lane = threadIdx.x & 31;
    if (row >= NN) return;
    const float* p = logits + (size_t)row * NCLS;
    float v0 = p[lane];
    float v1 = (lane < NCLS - 32) ? p[lane + 32] : -INFINITY;
    float mx = fmaxf(v0, v1);
    #pragma unroll
    for (int off = 16; off > 0; off >>= 1)
        mx = fmaxf(mx, __shfl_xor_sync(0xffffffffu, mx, off));
    float sm = expf(v0 - mx) + ((lane < NCLS - 32) ? expf(v1 - mx) : 0.f);
    #pragma unroll
    for (int off = 16; off > 0; off >>= 1)
        sm += __shfl_xor_sync(0xffffffffu, sm, off);
    float lse = mx + logf(sm);
    out[(size_t)row*NCLS + lane] = v0 - lse;
    if (lane < NCLS - 32) out[(size_t)row*NCLS + lane + 32] = v1 - lse;
}

// ---------------- host side ----------------
static inline void launch_gemm(const float* A, const float* B, float* C,
                               int M, int Nc, int Kc, int act) {
    dim3 grid((Nc + 127) / 128, (M + 127) / 128);
    sgemm128_k<<<grid, 256>>>(A, B, C, M, Nc, Kc, act);
}

extern "C" void kernel_launch(void* const* d_in, const int* in_sizes, int n_in,
                              void* d_out, int out_size) {
    const float* x     = (const float*)d_in[0];
    const int*   ei    = (const int*)d_in[1];      // int32 (JAX demotes int64)
    const float* w_in  = (const float*)d_in[2];
    const float* w_out = (const float*)d_in[3];
    const float* Wq    = (const float*)d_in[4];
    const float* Wk    = (const float*)d_in[5];
    const float* Wv    = (const float*)d_in[6];
    const float* Wm    = (const float*)d_in[7];
    const float* Wg    = (const float*)d_in[8];
    const float* Wo    = (const float*)d_in[9];
    float* out = (float*)d_out;

    const int* srcA = ei;
    const int* dstA = ei + EE;

    float *h, *h2, *qkvm, *wqkvm, *woin, *logits;
    int *cnt, *rowptr, *wptr, *esrc;
    cudaGetSymbolAddress((void**)&h,      g_h);
    cudaGetSymbolAddress((void**)&h2,     g_h2);
    cudaGetSymbolAddress((void**)&qkvm,   g_qkvm);
    cudaGetSymbolAddress((void**)&wqkvm,  g_wqkvm);
    cudaGetSymbolAddress((void**)&woin,   g_woin);
    cudaGetSymbolAddress((void**)&logits, g_logits);
    cudaGetSymbolAddress((void**)&cnt,    g_cnt);
    cudaGetSymbolAddress((void**)&rowptr, g_rowptr);
    cudaGetSymbolAddress((void**)&wptr,   g_wptr);
    cudaGetSymbolAddress((void**)&esrc,   g_esrc);

    // ---- CSR build (once per call, reused across layers) ----
    zero_cnt_k<<<(NN + 255) / 256, 256>>>(cnt);
    hist_k<<<(EE + 255) / 256, 256>>>(dstA, cnt);
    scan_k<<<1, 1024>>>(cnt, rowptr, wptr);
    scatter_k<<<(EE + 255) / 256, 256>>>(srcA, dstA, wptr, esrc);

    // h = x @ weight_in
    launch_gemm(x, w_in, h, NN, HID, FIN, 0);

    float* hcur = h;
    float* hnext = h2;

    for (int layer = 0; layer < 2; layer++) {
        const float* wq = Wq + (size_t)layer * HID * (KH*DA);
        const float* wk = Wk + (size_t)layer * HID * (KH*DA);
        const float* wv = Wv + (size_t)layer * HID * (KH*DV);
        const float* wm = Wm + (size_t)layer * HID * DM;
        const float* wg = Wg + (size_t)layer * 320 * KH;
        const float* wo = Wo + (size_t)layer * WO_IN * HID;

        pack_qkvm_k<<<(HID*QS2 + 255) / 256, 256>>>(wq, wk, wv, wm, wg, wqkvm);
        launch_gemm(hcur, wqkvm, qkvm, NN, QS2, HID, 0);    // q|k|v|m|gx|gm fused

        node_fused_k<<<(NN + 7) / 8, 256>>>(qkvm, hcur, rowptr, esrc, wg, woin);

        launch_gemm(woin, wo, hnext, NN, HID, WO_IN, 1);    // leaky_relu

        float* t = hcur; hcur = hnext; hnext = t;
    }

    // logits + log_softmax
    launch_gemm(hcur, w_out, logits, NN, NCLS, HID, 0);
    logsoftmax_k<<<(NN + 3) / 4, 128>>>(logits, out);
}

// round 9
// speedup vs baseline: 1.0180x; 1.0180x over previous
#include <cuda_runtime.h>
#include <math.h>

// ---------------- problem dims (fixed) ----------------
#define NN 50000
#define EE 600000
#define FIN 128
#define HID 128
#define KH 8
#define DA 16
#define DV 16
#define DM 64
#define NCLS 40
#define WO_IN  (HID + KH*DV)       // 256
#define QS2 464                    // q(128)|k(128)|v(128)|m(64)|gx(8)|gm(8)
#define QSH 592                    // QS2 + 128 (h appended, layer-0 combined)
#define SLOPE 0.1f

// ---------------- device scratch (no allocations allowed) ----------------
__device__ float g_qkvmh[(size_t)NN*QSH];   // layer0: qkvm|h ; layer1 reuses first 464 cols
__device__ float g_h2   [NN*HID];
__device__ float g_h3   [NN*HID];
__device__ float g_wqkvm[HID*QS2];
__device__ float g_wcomb[HID*QSH];
__device__ float g_woin [NN*WO_IN];
__device__ float g_logits[NN*NCLS];
__device__ int   g_cnt   [NN];
__device__ int   g_rowptr[NN+1];
__device__ int   g_wptr  [NN];
__device__ int   g_esrc  [EE];

// ---------------- f32x2 packed helpers ----------------
__device__ __forceinline__ unsigned long long fma2(unsigned long long a,
                                                   unsigned long long b,
                                                   unsigned long long c) {
    unsigned long long d;
    asm("fma.rn.f32x2 %0, %1, %2, %3;" : "=l"(d) : "l"(a), "l"(b), "l"(c));
    return d;
}
__device__ __forceinline__ unsigned long long dup2(float x) {
    unsigned long long d;
    asm("mov.b64 %0, {%1, %1};" : "=l"(d) : "f"(x));
    return d;
}
__device__ __forceinline__ void unpk2(unsigned long long d, float& lo, float& hi) {
    asm("mov.b64 {%0, %1}, %2;" : "=f"(lo), "=f"(hi) : "l"(d));
}

// ---------------- CSR build ----------------
__global__ void zero_cnt_k(int* cnt) {
    int i = blockIdx.x * blockDim.x + threadIdx.x;
    if (i < NN) cnt[i] = 0;
}
__global__ void hist_k(const int* __restrict__ dst, int* __restrict__ cnt) {
    int e = blockIdx.x * blockDim.x + threadIdx.x;
    if (e < EE) atomicAdd(&cnt[dst[e]], 1);
}
__global__ void scan_k(const int* __restrict__ cnt, int* __restrict__ rowptr,
                       int* __restrict__ wptr) {
    __shared__ int ps[1024];
    const int C = (NN + 1023) / 1024;
    int t = threadIdx.x;
    int base = t * C;
    int sum = 0;
    for (int j = 0; j < C; j++) {
        int idx = base + j;
        if (idx < NN) sum += cnt[idx];
    }
    ps[t] = sum; __syncthreads();
    for (int off = 1; off < 1024; off <<= 1) {
        int v = (t >= off) ? ps[t - off] : 0;
        __syncthreads();
        ps[t] += v;
        __syncthreads();
    }
    int running = ps[t] - sum;
    if (t == 0) rowptr[0] = 0;
    for (int j = 0; j < C; j++) {
        int idx = base + j;
        if (idx < NN) {
            wptr[idx] = running;
            running += cnt[idx];
            rowptr[idx + 1] = running;
        }
    }
}
__global__ void scatter_k(const int* __restrict__ src, const int* __restrict__ dst,
                          int* __restrict__ wptr, int* __restrict__ esrc) {
    int e = blockIdx.x * blockDim.x + threadIdx.x;
    if (e < EE) {
        int pos = atomicAdd(&wptr[dst[e]], 1);
        esrc[pos] = src[e];
    }
}

// pack layer weights [128 x 464] = [Wq | Wk | Wv | Wm | Wg_x | Wg_mean]
__global__ void pack_qkvm_k(const float* __restrict__ Wq, const float* __restrict__ Wk,
                            const float* __restrict__ Wv, const float* __restrict__ Wm,
                            const float* __restrict__ Wg, float* __restrict__ Bf) {
    int idx = blockIdx.x * blockDim.x + threadIdx.x;
    if (idx >= HID*QS2) return;
    int r = idx / QS2, c = idx % QS2;
    float v;
    if      (c < 128) v = Wq[r*128 + c];
    else if (c < 256) v = Wk[r*128 + (c-128)];
    else if (c < 384) v = Wv[r*128 + (c-256)];
    else if (c < 448) v = Wm[r*64  + (c-384)];
    else if (c < 456) v = Wg[r*KH + (c-448)];            // x rows of Wg
    else              v = Wg[(192 + r)*KH + (c-456)];    // mean rows of Wg
    Bf[idx] = v;
}

// compose layer-0 combined weight [128 x 592] = [W_in @ Wp | W_in]
__global__ void compose_k(const float* __restrict__ Win, const float* __restrict__ Wp,
                          float* __restrict__ Wc) {
    int idx = blockIdx.x * blockDim.x + threadIdx.x;
    if (idx >= HID*QSH) return;
    int r = idx / QSH, c = idx % QSH;
    if (c < QS2) {
        float s = 0.f;
        const float* wr = Win + r*128;
        #pragma unroll 8
        for (int j = 0; j < 128; j++) s += wr[j] * Wp[j*QS2 + c];
        Wc[idx] = s;
    } else {
        Wc[idx] = Win[r*128 + (c - QS2)];
    }
}

// ---------------- 128x128x16 SGEMM, 8x8 microtile, f32x2, double-buffered ----
// Requires: Kc % 16 == 0, Nc % 4 == 0.
__global__ __launch_bounds__(256, 2)
void sgemm128_k(const float* __restrict__ A, const float* __restrict__ B,
                float* __restrict__ C, int M, int Nc, int Kc, int act) {
    __shared__ float As[2][16][128];
    __shared__ float Bs[2][16][128];
    int tid = threadIdx.x;
    int tx = tid & 15, ty = tid >> 4;
    int rowBase = blockIdx.y * 128;
    int colBase = blockIdx.x * 128;

    int arow  = tid >> 1;
    int acol4 = (tid & 1) * 4;
    int brow  = tid >> 5;
    int bcol4 = (tid & 31) * 4;
    int agr = rowBase + arow;
    int bgc = colBase + bcol4;

    float4 pa[2], pb[2];

    #pragma unroll
    for (int half = 0; half < 2; half++) {
        int ac = acol4 + half * 8;
        pa[half] = make_float4(0.f, 0.f, 0.f, 0.f);
        if (agr < M) pa[half] = *(const float4*)(A + (size_t)agr*Kc + ac);
        pb[half] = make_float4(0.f, 0.f, 0.f, 0.f);
        if (bgc < Nc) pb[half] = *(const float4*)(B + (size_t)(brow + half*8)*Nc + bgc);
    }
    #pragma unroll
    for (int half = 0; half < 2; half++) {
        int ac = acol4 + half * 8;
        As[0][ac+0][arow] = pa[half].x;
        As[0][ac+1][arow] = pa[half].y;
        As[0][ac+2][arow] = pa[half].z;
        As[0][ac+3][arow] = pa[half].w;
        *(float4*)&Bs[0][brow + half*8][bcol4] = pb[half];
    }
    __syncthreads();

    unsigned long long acc2[8][4];
    #pragma unroll
    for (int i = 0; i < 8; i++)
        #pragma unroll
        for (int j = 0; j < 4; j++) acc2[i][j] = 0ull;

    int nchunks = Kc >> 4;
    for (int c = 0; c < nchunks; c++) {
        int cur = c & 1;
        if (c + 1 < nchunks) {
            int k0 = (c + 1) << 4;
            #pragma unroll
            for (int half = 0; half < 2; half++) {
                int ac = acol4 + half * 8;
                pa[half] = make_float4(0.f, 0.f, 0.f, 0.f);
                if (agr < M) pa[half] = *(const float4*)(A + (size_t)agr*Kc + k0 + ac);
                pb[half] = make_float4(0.f, 0.f, 0.f, 0.f);
                if (bgc < Nc) pb[half] = *(const float4*)(B + (size_t)(k0 + brow + half*8)*Nc + bgc);
            }
        }
        #pragma unroll
        for (int kk = 0; kk < 16; kk++) {
            float4 a0 = *(const float4*)&As[cur][kk][ty*4];
            float4 a1 = *(const float4*)&As[cur][kk][64 + ty*4];
            const unsigned long long* bp0 = (const unsigned long long*)&Bs[cur][kk][tx*4];
            const unsigned long long* bp1 = (const unsigned long long*)&Bs[cur][kk][64 + tx*4];
            unsigned long long b2[4] = {bp0[0], bp0[1], bp1[0], bp1[1]};
            float a[8] = {a0.x,a0.y,a0.z,a0.w, a1.x,a1.y,a1.z,a1.w};
            #pragma unroll
            for (int i = 0; i < 8; i++) {
                unsigned long long ad = dup2(a[i]);
                acc2[i][0] = fma2(ad, b2[0], acc2[i][0]);
                acc2[i][1] = fma2(ad, b2[1], acc2[i][1]);
                acc2[i][2] = fma2(ad, b2[2], acc2[i][2]);
                acc2[i][3] = fma2(ad, b2[3], acc2[i][3]);
            }
        }
        if (c + 1 < nchunks) {
            int nxt = cur ^ 1;
            #pragma unroll
            for (int half = 0; half < 2; half++) {
                int ac = acol4 + half * 8;
                As[nxt][ac+0][arow] = pa[half].x;
                As[nxt][ac+1][arow] = pa[half].y;
                As[nxt][ac+2][arow] = pa[half].z;
                As[nxt][ac+3][arow] = pa[half].w;
                *(float4*)&Bs[nxt][brow + half*8][bcol4] = pb[half];
            }
        }
        __syncthreads();
    }

    #pragma unroll
    for (int ih = 0; ih < 2; ih++) {
        #pragma unroll
        for (int i = 0; i < 4; i++) {
            int gr = rowBase + ih*64 + ty*4 + i;
            if (gr >= M) continue;
            #pragma unroll
            for (int jh = 0; jh < 2; jh++) {
                int gc = colBase + jh*64 + tx*4;
                if (gc >= Nc) continue;
                float4 vv;
                unpk2(acc2[ih*4+i][jh*2+0], vv.x, vv.y);
                unpk2(acc2[ih*4+i][jh*2+1], vv.z, vv.w);
                if (act == 1) {
                    vv.x = vv.x > 0.f ? vv.x : SLOPE*vv.x;
                    vv.y = vv.y > 0.f ? vv.y : SLOPE*vv.y;
                    vv.z = vv.z > 0.f ? vv.z : SLOPE*vv.z;
                    vv.w = vv.w > 0.f ? vv.w : SLOPE*vv.w;
                }
                *(float4*)(C + (size_t)gr*Nc + gc) = vv;
            }
        }
    }
}

// ---------------- fused node kernel: attn+pool+gate+woin ----------------
// warp per node; online softmax; single accumulator + next-edge register prefetch.
// qkvm has row stride qs; h has row stride hs.
__global__ __launch_bounds__(256)
void node_fused_k(const float* __restrict__ qkvm, int qs,
                  const float* __restrict__ h, int hs,
                  const int* __restrict__ rowptr, const int* __restrict__ esrc,
                  const float* __restrict__ Wg, float* __restrict__ woin) {
    __shared__ float Ws[DM][KH+1];        // maxpool rows of Wg (64x8), padded
    int tid = threadIdx.x;                // 256
    for (int i = tid; i < DM*KH; i += 256) Ws[i/KH][i%KH] = Wg[(128 + i/KH)*KH + (i%KH)];
    __syncthreads();

    int warp = tid >> 5, lane = tid & 31;
    int n = blockIdx.x * 8 + warp;
    if (n >= NN) return;
    int head = lane >> 2;

    float4 q4 = *(const float4*)(qkvm + (size_t)n*qs + lane*4);   // q
    int start = rowptr[n], end = rowptr[n+1];
    int cnt = end - start;

    float smx = -INFINITY, denom = 0.f;
    float4 acc = make_float4(0.f, 0.f, 0.f, 0.f);
    float mx0 = -INFINITY, mx1 = -INFINITY;
    float gmsum = 0.f;

    // prefetch staging
    float4 kC, vC;
    float m0C = 0.f, m1C = 0.f, gC = 0.f;
    if (start < end) {
        const float* b0 = qkvm + (size_t)esrc[start]*qs;
        kC  = *(const float4*)(b0 + 128 + lane*4);
        vC  = *(const float4*)(b0 + 256 + lane*4);
        m0C = b0[384 + lane]; m1C = b0[416 + lane]; gC = b0[456 + head];
    }

    for (int i = start; i < end; i++) {
        float4 k4 = kC, v4 = vC;
        float m0 = m0C, m1 = m1C, gm = gC;
        if (i + 1 < end) {                   // issue next-edge loads early
            const float* bn = qkvm + (size_t)esrc[i+1]*qs;
            kC  = *(const float4*)(bn + 128 + lane*4);
            vC  = *(const float4*)(bn + 256 + lane*4);
            m0C = bn[384 + lane]; m1C = bn[416 + lane]; gC = bn[456 + head];
        }
        float p = q4.x*k4.x + q4.y*k4.y + q4.z*k4.z + q4.w*k4.w;
        p += __shfl_xor_sync(0xffffffffu, p, 1);
        p += __shfl_xor_sync(0xffffffffu, p, 2);
        float nm = fmaxf(smx, p);
        float sc = __expf(smx - nm), ex = __expf(p - nm);
        denom = denom*sc + ex;
        acc.x = acc.x*sc + ex*v4.x;
        acc.y = acc.y*sc + ex*v4.y;
        acc.z = acc.z*sc + ex*v4.z;
        acc.w = acc.w*sc + ex*v4.w;
        smx = nm;
        mx0 = fmaxf(mx0, m0);
        mx1 = fmaxf(mx1, m1);
        gmsum += gm;
    }

    float inv = 1.f / (denom + 1e-16f);
    float4 o = make_float4(acc.x*inv, acc.y*inv, acc.z*inv, acc.w*inv);  // agg

    float mp0 = cnt ? mx0 : 0.f, mp1 = cnt ? mx1 : 0.f;
    float invd = 1.f / fmaxf((float)cnt, 1.f);

    // gate FC over maxpool (64 dims spread over lanes)
    float ga[KH] = {};
    #pragma unroll
    for (int oo = 0; oo < KH; oo++)
        ga[oo] = mp0 * Ws[lane][oo] + mp1 * Ws[lane + 32][oo];
    #pragma unroll
    for (int oo = 0; oo < KH; oo++)
        #pragma unroll
        for (int off = 16; off; off >>= 1)
            ga[oo] += __shfl_xor_sync(0xffffffffu, ga[oo], off);

    float gsum = ga[0];
    #pragma unroll
    for (int oo = 1; oo < KH; oo++) if (head == oo) gsum = ga[oo];
    gsum += qkvm[(size_t)n*qs + 448 + head];     // x part of gate
    gsum += gmsum * invd;                        // mean part of gate
    float gh = 1.f / (1.f + expf(-gsum));

    // write woin row: [h | g*agg]
    const float* hn = h + (size_t)n*hs;
    float* w = woin + (size_t)n*WO_IN;
    *(float4*)(w + lane*4) = *(const float4*)(hn + lane*4);
    *(float4*)(w + 128 + lane*4) = make_float4(gh*o.x, gh*o.y, gh*o.z, gh*o.w);
}

// row-wise log_softmax over 40 classes; one warp per row
__global__ void logsoftmax_k(const float* __restrict__ logits, float* __restrict__ out) {
    int row = blockIdx.x * 4 + (threadIdx.x >> 5);
    int lane = threadIdx.x & 31;
    if (row >= NN) return;
    const float* p = logits + (size_t)row * NCLS;
    float v0 = p[lane];
    float v1 = (lane < NCLS - 32) ? p[lane + 32] : -INFINITY;
    float mx = fmaxf(v0, v1);
    #pragma unroll
    for (int off = 16; off > 0; off >>= 1)
        mx = fmaxf(mx, __shfl_xor_sync(0xffffffffu, mx, off));
    float sm = expf(v0 - mx) + ((lane < NCLS - 32) ? expf(v1 - mx) : 0.f);
    #pragma unroll
    for (int off = 16; off > 0; off >>= 1)
        sm += __shfl_xor_sync(0xffffffffu, sm, off);
    float lse = mx + logf(sm);
    out[(size_t)row*NCLS + lane] = v0 - lse;
    if (lane < NCLS - 32) out[(size_t)row*NCLS + lane + 32] = v1 - lse;
}

// ---------------- host side ----------------
static inline void launch_gemm(const float* A, const float* B, float* C,
                               int M, int Nc, int Kc, int act) {
    dim3 grid((Nc + 127) / 128, (M + 127) / 128);
    sgemm128_k<<<grid, 256>>>(A, B, C, M, Nc, Kc, act);
}

extern "C" void kernel_launch(void* const* d_in, const int* in_sizes, int n_in,
                              void* d_out, int out_size) {
    const float* x     = (const float*)d_in[0];
    const int*   ei    = (const int*)d_in[1];      // int32 (JAX demotes int64)
    const float* w_in  = (const float*)d_in[2];
    const float* w_out = (const float*)d_in[3];
    const float* Wq    = (const float*)d_in[4];
    const float* Wk    = (const float*)d_in[5];
    const float* Wv    = (const float*)d_in[6];
    const float* Wm    = (const float*)d_in[7];
    const float* Wg    = (const float*)d_in[8];
    const float* Wo    = (const float*)d_in[9];
    float* out = (float*)d_out;

    const int* srcA = ei;
    const int* dstA = ei + EE;

    float *qkvmh, *h2, *h3, *wqkvm, *wcomb, *woin, *logits;
    int *cnt, *rowptr, *wptr, *esrc;
    cudaGetSymbolAddress((void**)&qkvmh,  g_qkvmh);
    cudaGetSymbolAddress((void**)&h2,     g_h2);
    cudaGetSymbolAddress((void**)&h3,     g_h3);
    cudaGetSymbolAddress((void**)&wqkvm,  g_wqkvm);
    cudaGetSymbolAddress((void**)&wcomb,  g_wcomb);
    cudaGetSymbolAddress((void**)&woin,   g_woin);
    cudaGetSymbolAddress((void**)&logits, g_logits);
    cudaGetSymbolAddress((void**)&cnt,    g_cnt);
    cudaGetSymbolAddress((void**)&rowptr, g_rowptr);
    cudaGetSymbolAddress((void**)&wptr,   g_wptr);
    cudaGetSymbolAddress((void**)&esrc,   g_esrc);

    // ---- CSR build (once per call, reused across layers) ----
    zero_cnt_k<<<(NN + 255) / 256, 256>>>(cnt);
    hist_k<<<(EE + 255) / 256, 256>>>(dstA, cnt);
    scan_k<<<1, 1024>>>(cnt, rowptr, wptr);
    scatter_k<<<(EE + 255) / 256, 256>>>(srcA, dstA, wptr, esrc);

    // ---- layer 0: combined x @ [W_in@Wp | W_in] -> qkvm|h in one buffer ----
    {
        const float* wg0 = Wg;                               // layer 0 Wg
        pack_qkvm_k<<<(HID*QS2 + 255) / 256, 256>>>(Wq, Wk, Wv, Wm, wg0, wqkvm);
        compose_k<<<(HID*QSH + 255) / 256, 256>>>(w_in, wqkvm, wcomb);
        launch_gemm(x, wcomb, qkvmh, NN, QSH, HID, 0);       // qkvm(464)|h(128)

        node_fused_k<<<(NN + 7) / 8, 256>>>(qkvmh, QSH, qkvmh + QS2, QSH,
                                            rowptr, esrc, wg0, woin);
        launch_gemm(woin, Wo, h2, NN, HID, WO_IN, 1);        // leaky_relu
    }

    // ---- layer 1 ----
    {
        const float* wq = Wq + (size_t)HID * (KH*DA);
        const float* wk = Wk + (size_t)HID * (KH*DA);
        const float* wv = Wv + (size_t)HID * (KH*DV);
        const float* wm = Wm + (size_t)HID * DM;
        const float* wg = Wg + (size_t)320 * KH;
        const float* wo = Wo + (size_t)WO_IN * HID;

        pack_qkvm_k<<<(HID*QS2 + 255) / 256, 256>>>(wq, wk, wv, wm, wg, wqkvm);
        launch_gemm(h2, wqkvm, qkvmh, NN, QS2, HID, 0);      // reuse buffer, stride 464

        node_fused_k<<<(NN + 7) / 8, 256>>>(qkvmh, QS2, h2, HID,
                                            rowptr, esrc, wg, woin);
        launch_gemm(woin, wo, h3, NN, HID, WO_IN, 1);        // leaky_relu
    }

    // logits + log_softmax
    launch_gemm(h3, w_out, logits, NN, NCLS, HID, 0);
    logsoftmax_k<<<(NN + 3) / 4, 128>>>(logits, out);
}

// round 10
// speedup vs baseline: 1.1221x; 1.1024x over previous
#include <cuda_runtime.h>
#include <math.h>

// ---------------- problem dims (fixed) ----------------
#define NN 50000
#define EE 600000
#define FIN 128
#define HID 128
#define KH 8
#define DA 16
#define DV 16
#define DM 64
#define NCLS 40
#define WO_IN  (HID + KH*DV)       // 256
#define QS3 480                    // q(128)|k(128)|v(128)|m(64)|gx(8)|gm(8)|pad(16)
                                   // 480 floats = 1920 B = 15 cache lines (aligned)
#define SLOPE 0.1f
#define NB 49                      // scan blocks: ceil(NN/1024)

// ---------------- device scratch (no allocations allowed) ----------------
__device__ float g_h    [NN*HID];
__device__ float g_h2   [NN*HID];
__device__ float g_qkvm [(size_t)NN*QS3];
__device__ float g_wqkvm[HID*QS3];
__device__ float g_woin [NN*WO_IN];
__device__ float g_logits[NN*NCLS];
__device__ int   g_cnt   [NN];
__device__ int   g_rowptr[NN+1];
__device__ int   g_wptr  [NN];
__device__ int   g_esrc  [EE];
__device__ int   g_bsum  [64];
__device__ int   g_boff  [64];

// ---------------- f32x2 packed helpers ----------------
__device__ __forceinline__ unsigned long long fma2(unsigned long long a,
                                                   unsigned long long b,
                                                   unsigned long long c) {
    unsigned long long d;
    asm("fma.rn.f32x2 %0, %1, %2, %3;" : "=l"(d) : "l"(a), "l"(b), "l"(c));
    return d;
}
__device__ __forceinline__ unsigned long long dup2(float x) {
    unsigned long long d;
    asm("mov.b64 %0, {%1, %1};" : "=l"(d) : "f"(x));
    return d;
}
__device__ __forceinline__ void unpk2(unsigned long long d, float& lo, float& hi) {
    asm("mov.b64 {%0, %1}, %2;" : "=f"(lo), "=f"(hi) : "l"(d));
}

// ---------------- CSR build ----------------
__global__ void zero_cnt_k(int* cnt) {
    int i = blockIdx.x * blockDim.x + threadIdx.x;
    if (i < NN) cnt[i] = 0;
}
__global__ void hist_k(const int* __restrict__ dst, int* __restrict__ cnt) {
    int e = blockIdx.x * blockDim.x + threadIdx.x;
    if (e < EE) atomicAdd(&cnt[dst[e]], 1);
}
// blockwise inclusive scan -> rowptr[i+1]; block sums -> bsum
__global__ void scan_a_k(const int* __restrict__ cnt, int* __restrict__ rowptr,
                         int* __restrict__ bsum) {
    __shared__ int sh[1024];
    int t = threadIdx.x;
    int i = blockIdx.x * 1024 + t;
    int v = (i < NN) ? cnt[i] : 0;
    sh[t] = v; __syncthreads();
    #pragma unroll
    for (int off = 1; off < 1024; off <<= 1) {
        int u = (t >= off) ? sh[t - off] : 0;
        __syncthreads();
        sh[t] += u;
        __syncthreads();
    }
    if (i < NN) rowptr[i + 1] = sh[t];
    if (t == 1023) bsum[blockIdx.x] = sh[t];
}
// scan the 49 block sums (single tiny block)
__global__ void scan_b_k(const int* __restrict__ bsum, int* __restrict__ boff) {
    if (threadIdx.x == 0) {
        int run = 0;
        for (int b = 0; b < NB; b++) { boff[b] = run; run += bsum[b]; }
    }
}
// fixup: add block offsets, derive wptr
__global__ void scan_c_k(const int* __restrict__ cnt, const int* __restrict__ boff,
                         int* __restrict__ rowptr, int* __restrict__ wptr) {
    int t = threadIdx.x;
    int i = blockIdx.x * 1024 + t;
    if (i == 0) rowptr[0] = 0;
    if (i < NN) {
        int e = rowptr[i + 1] + boff[blockIdx.x];
        rowptr[i + 1] = e;
        wptr[i] = e - cnt[i];
    }
}
__global__ void scatter_k(const int* __restrict__ src, const int* __restrict__ dst,
                          int* __restrict__ wptr, int* __restrict__ esrc) {
    int e = blockIdx.x * blockDim.x + threadIdx.x;
    if (e < EE) {
        int pos = atomicAdd(&wptr[dst[e]], 1);
        esrc[pos] = src[e];
    }
}

// pack layer weights [128 x 480] = [Wq | Wk | Wv | Wm | Wg_x | Wg_mean | 0pad]
__global__ void pack_qkvm_k(const float* __restrict__ Wq, const float* __restrict__ Wk,
                            const float* __restrict__ Wv, const float* __restrict__ Wm,
                            const float* __restrict__ Wg, float* __restrict__ Bf) {
    int idx = blockIdx.x * blockDim.x + threadIdx.x;
    if (idx >= HID*QS3) return;
    int r = idx / QS3, c = idx % QS3;
    float v;
    if      (c < 128) v = Wq[r*128 + c];
    else if (c < 256) v = Wk[r*128 + (c-128)];
    else if (c < 384) v = Wv[r*128 + (c-256)];
    else if (c < 448) v = Wm[r*64  + (c-384)];
    else if (c < 456) v = Wg[r*KH + (c-448)];            // x rows of Wg
    else if (c < 464) v = Wg[(192 + r)*KH + (c-456)];    // mean rows of Wg
    else              v = 0.f;                           // pad
    Bf[idx] = v;
}

// ---------------- 128x128x16 SGEMM, 8x8 microtile, f32x2, double-buffered ----
// Requires: Kc % 16 == 0, Nc % 4 == 0.
__global__ __launch_bounds__(256, 2)
void sgemm128_k(const float* __restrict__ A, const float* __restrict__ B,
                float* __restrict__ C, int M, int Nc, int Kc, int act) {
    __shared__ float As[2][16][128];
    __shared__ float Bs[2][16][128];
    int tid = threadIdx.x;
    int tx = tid & 15, ty = tid >> 4;
    int rowBase = blockIdx.y * 128;
    int colBase = blockIdx.x * 128;

    int arow  = tid >> 1;
    int acol4 = (tid & 1) * 4;
    int brow  = tid >> 5;
    int bcol4 = (tid & 31) * 4;
    int agr = rowBase + arow;
    int bgc = colBase + bcol4;

    float4 pa[2], pb[2];

    #pragma unroll
    for (int half = 0; half < 2; half++) {
        int ac = acol4 + half * 8;
        pa[half] = make_float4(0.f, 0.f, 0.f, 0.f);
        if (agr < M) pa[half] = *(const float4*)(A + (size_t)agr*Kc + ac);
        pb[half] = make_float4(0.f, 0.f, 0.f, 0.f);
        if (bgc < Nc) pb[half] = *(const float4*)(B + (size_t)(brow + half*8)*Nc + bgc);
    }
    #pragma unroll
    for (int half = 0; half < 2; half++) {
        int ac = acol4 + half * 8;
        As[0][ac+0][arow] = pa[half].x;
        As[0][ac+1][arow] = pa[half].y;
        As[0][ac+2][arow] = pa[half].z;
        As[0][ac+3][arow] = pa[half].w;
        *(float4*)&Bs[0][brow + half*8][bcol4] = pb[half];
    }
    __syncthreads();

    unsigned long long acc2[8][4];
    #pragma unroll
    for (int i = 0; i < 8; i++)
        #pragma unroll
        for (int j = 0; j < 4; j++) acc2[i][j] = 0ull;

    int nchunks = Kc >> 4;
    for (int c = 0; c < nchunks; c++) {
        int cur = c & 1;
        if (c + 1 < nchunks) {
            int k0 = (c + 1) << 4;
            #pragma unroll
            for (int half = 0; half < 2; half++) {
                int ac = acol4 + half * 8;
                pa[half] = make_float4(0.f, 0.f, 0.f, 0.f);
                if (agr < M) pa[half] = *(const float4*)(A + (size_t)agr*Kc + k0 + ac);
                pb[half] = make_float4(0.f, 0.f, 0.f, 0.f);
                if (bgc < Nc) pb[half] = *(const float4*)(B + (size_t)(k0 + brow + half*8)*Nc + bgc);
            }
        }
        #pragma unroll
        for (int kk = 0; kk < 16; kk++) {
            float4 a0 = *(const float4*)&As[cur][kk][ty*4];
            float4 a1 = *(const float4*)&As[cur][kk][64 + ty*4];
            const unsigned long long* bp0 = (const unsigned long long*)&Bs[cur][kk][tx*4];
            const unsigned long long* bp1 = (const unsigned long long*)&Bs[cur][kk][64 + tx*4];
            unsigned long long b2[4] = {bp0[0], bp0[1], bp1[0], bp1[1]};
            float a[8] = {a0.x,a0.y,a0.z,a0.w, a1.x,a1.y,a1.z,a1.w};
            #pragma unroll
            for (int i = 0; i < 8; i++) {
                unsigned long long ad = dup2(a[i]);
                acc2[i][0] = fma2(ad, b2[0], acc2[i][0]);
                acc2[i][1] = fma2(ad, b2[1], acc2[i][1]);
                acc2[i][2] = fma2(ad, b2[2], acc2[i][2]);
                acc2[i][3] = fma2(ad, b2[3], acc2[i][3]);
            }
        }
        if (c + 1 < nchunks) {
            int nxt = cur ^ 1;
            #pragma unroll
            for (int half = 0; half < 2; half++) {
                int ac = acol4 + half * 8;
                As[nxt][ac+0][arow] = pa[half].x;
                As[nxt][ac+1][arow] = pa[half].y;
                As[nxt][ac+2][arow] = pa[half].z;
                As[nxt][ac+3][arow] = pa[half].w;
                *(float4*)&Bs[nxt][brow + half*8][bcol4] = pb[half];
            }
        }
        __syncthreads();
    }

    #pragma unroll
    for (int ih = 0; ih < 2; ih++) {
        #pragma unroll
        for (int i = 0; i < 4; i++) {
            int gr = rowBase + ih*64 + ty*4 + i;
            if (gr >= M) continue;
            #pragma unroll
            for (int jh = 0; jh < 2; jh++) {
                int gc = colBase + jh*64 + tx*4;
                if (gc >= Nc) continue;
                float4 vv;
                unpk2(acc2[ih*4+i][jh*2+0], vv.x, vv.y);
                unpk2(acc2[ih*4+i][jh*2+1], vv.z, vv.w);
                if (act == 1) {
                    vv.x = vv.x > 0.f ? vv.x : SLOPE*vv.x;
                    vv.y = vv.y > 0.f ? vv.y : SLOPE*vv.y;
                    vv.z = vv.z > 0.f ? vv.z : SLOPE*vv.z;
                    vv.w = vv.w > 0.f ? vv.w : SLOPE*vv.w;
                }
                *(float4*)(C + (size_t)gr*Nc + gc) = vv;
            }
        }
    }
}

// ---------------- fused node kernel: attn+pool+gate+woin ----------------
// warp per node; online softmax; single accumulator (proven best schedule).
__global__ __launch_bounds__(256)
void node_fused_k(const float* __restrict__ qkvm, const float* __restrict__ h,
                  const int* __restrict__ rowptr, const int* __restrict__ esrc,
                  const float* __restrict__ Wg, float* __restrict__ woin) {
    __shared__ float Ws[DM][KH+1];        // maxpool rows of Wg (64x8), padded
    int tid = threadIdx.x;                // 256
    for (int i = tid; i < DM*KH; i += 256) Ws[i/KH][i%KH] = Wg[(128 + i/KH)*KH + (i%KH)];
    __syncthreads();

    int warp = tid >> 5, lane = tid & 31;
    int n = blockIdx.x * 8 + warp;
    if (n >= NN) return;
    int head = lane >> 2;

    float4 q4 = *(const float4*)(qkvm + (size_t)n*QS3 + lane*4);   // q
    int start = rowptr[n], end = rowptr[n+1];
    int cnt = end - start;

    float smx = -INFINITY, denom = 0.f;
    float4 acc = make_float4(0.f, 0.f, 0.f, 0.f);
    float mx0 = -INFINITY, mx1 = -INFINITY;
    float gmsum = 0.f;

    for (int i = start; i < end; i++) {
        int s = esrc[i];
        const float* base = qkvm + (size_t)s*QS3;
        float4 k4 = *(const float4*)(base + 128 + lane*4);
        float p = q4.x*k4.x + q4.y*k4.y + q4.z*k4.z + q4.w*k4.w;
        p += __shfl_xor_sync(0xffffffffu, p, 1);
        p += __shfl_xor_sync(0xffffffffu, p, 2);
        float nm = fmaxf(smx, p);
        float sc = __expf(smx - nm), ex = __expf(p - nm);
        denom = denom*sc + ex;
        float4 v4 = *(const float4*)(base + 256 + lane*4);
        acc.x = acc.x*sc + ex*v4.x;
        acc.y = acc.y*sc + ex*v4.y;
        acc.z = acc.z*sc + ex*v4.z;
        acc.w = acc.w*sc + ex*v4.w;
        smx = nm;
        mx0 = fmaxf(mx0, base[384 + lane]);
        mx1 = fmaxf(mx1, base[416 + lane]);
        gmsum += base[456 + head];
    }

    float inv = 1.f / (denom + 1e-16f);
    float4 o = make_float4(acc.x*inv, acc.y*inv, acc.z*inv, acc.w*inv);  // agg

    float mp0 = cnt ? mx0 : 0.f, mp1 = cnt ? mx1 : 0.f;
    float invd = 1.f / fmaxf((float)cnt, 1.f);

    // gate FC over maxpool (64 dims spread over lanes)
    float ga[KH] = {};
    #pragma unroll
    for (int oo = 0; oo < KH; oo++)
        ga[oo] = mp0 * Ws[lane][oo] + mp1 * Ws[lane + 32][oo];
    #pragma unroll
    for (int oo = 0; oo < KH; oo++)
        #pragma unroll
        for (int off = 16; off; off >>= 1)
            ga[oo] += __shfl_xor_sync(0xffffffffu, ga[oo], off);

    float gsum = ga[0];
    #pragma unroll
    for (int oo = 1; oo < KH; oo++) if (head == oo) gsum = ga[oo];
    gsum += qkvm[(size_t)n*QS3 + 448 + head];    // x part of gate
    gsum += gmsum * invd;                        // mean part of gate
    float gh = 1.f / (1.f + expf(-gsum));

    // write woin row: [h | g*agg]
    const float* hn = h + (size_t)n*HID;
    float* w = woin + (size_t)n*WO_IN;
    *(float4*)(w + lane*4) = *(const float4*)(hn + lane*4);
    *(float4*)(w + 128 + lane*4) = make_float4(gh*o.x, gh*o.y, gh*o.z, gh*o.w);
}

// row-wise log_softmax over 40 classes; one warp per row
__global__ void logsoftmax_k(const float* __restrict__ logits, float* __restrict__ out) {
    int row = blockIdx.x * 4 + (threadIdx.x >> 5);
    int lane = threadIdx.x & 31;
    if (row >= NN) return;
    const float* p = logits + (size_t)row * NCLS;
    float v0 = p[lane];
    float v1 = (lane < NCLS - 32) ? p[lane + 32] : -INFINITY;
    float mx = fmaxf(v0, v1);
    #pragma unroll
    for (int off = 16; off > 0; off >>= 1)
        mx = fmaxf(mx, __shfl_xor_sync(0xffffffffu, mx, off));
    float sm = expf(v0 - mx) + ((lane < NCLS - 32) ? expf(v1 - mx) : 0.f);
    #pragma unroll
    for (int off = 16; off > 0; off >>= 1)
        sm += __shfl_xor_sync(0xffffffffu, sm, off);
    float lse = mx + logf(sm);
    out[(size_t)row*NCLS + lane] = v0 - lse;
    if (lane < NCLS - 32) out[(size_t)row*NCLS + lane + 32] = v1 - lse;
}

// ---------------- host side ----------------
static inline void launch_gemm(const float* A, const float* B, float* C,
                               int M, int Nc, int Kc, int act) {
    dim3 grid((Nc + 127) / 128, (M + 127) / 128);
    sgemm128_k<<<grid, 256>>>(A, B, C, M, Nc, Kc, act);
}

extern "C" void kernel_launch(void* const* d_in, const int* in_sizes, int n_in,
                              void* d_out, int out_size) {
    const float* x     = (const float*)d_in[0];
    const int*   ei    = (const int*)d_in[1];      // int32 (JAX demotes int64)
    const float* w_in  = (const float*)d_in[2];
    const float* w_out = (const float*)d_in[3];
    const float* Wq    = (const float*)d_in[4];
    const float* Wk    = (const float*)d_in[5];
    const float* Wv    = (const float*)d_in[6];
    const float* Wm    = (const float*)d_in[7];
    const float* Wg    = (const float*)d_in[8];
    const float* Wo    = (const float*)d_in[9];
    float* out = (float*)d_out;

    const int* srcA = ei;
    const int* dstA = ei + EE;

    float *h, *h2, *qkvm, *wqkvm, *woin, *logits;
    int *cnt, *rowptr, *wptr, *esrc, *bsum, *boff;
    cudaGetSymbolAddress((void**)&h,      g_h);
    cudaGetSymbolAddress((void**)&h2,     g_h2);
    cudaGetSymbolAddress((void**)&qkvm,   g_qkvm);
    cudaGetSymbolAddress((void**)&wqkvm,  g_wqkvm);
    cudaGetSymbolAddress((void**)&woin,   g_woin);
    cudaGetSymbolAddress((void**)&logits, g_logits);
    cudaGetSymbolAddress((void**)&cnt,    g_cnt);
    cudaGetSymbolAddress((void**)&rowptr, g_rowptr);
    cudaGetSymbolAddress((void**)&wptr,   g_wptr);
    cudaGetSymbolAddress((void**)&esrc,   g_esrc);
    cudaGetSymbolAddress((void**)&bsum,   g_bsum);
    cudaGetSymbolAddress((void**)&boff,   g_boff);

    // ---- CSR build (once per call, reused across layers) ----
    zero_cnt_k<<<(NN + 255) / 256, 256>>>(cnt);
    hist_k<<<(EE + 255) / 256, 256>>>(dstA, cnt);
    scan_a_k<<<NB, 1024>>>(cnt, rowptr, bsum);
    scan_b_k<<<1, 32>>>(bsum, boff);
    scan_c_k<<<NB, 1024>>>(cnt, boff, rowptr, wptr);
    scatter_k<<<(EE + 255) / 256, 256>>>(srcA, dstA, wptr, esrc);

    // h = x @ weight_in
    launch_gemm(x, w_in, h, NN, HID, FIN, 0);

    float* hcur = h;
    float* hnext = h2;

    for (int layer = 0; layer < 2; layer++) {
        const float* wq = Wq + (size_t)layer * HID * (KH*DA);
        const float* wk = Wk + (size_t)layer * HID * (KH*DA);
        const float* wv = Wv + (size_t)layer * HID * (KH*DV);
        const float* wm = Wm + (size_t)layer * HID * DM;
        const float* wg = Wg + (size_t)layer * 320 * KH;
        const float* wo = Wo + (size_t)layer * WO_IN * HID;

        pack_qkvm_k<<<(HID*QS3 + 255) / 256, 256>>>(wq, wk, wv, wm, wg, wqkvm);
        launch_gemm(hcur, wqkvm, qkvm, NN, QS3, HID, 0);    // q|k|v|m|gx|gm fused

        node_fused_k<<<(NN + 7) / 8, 256>>>(qkvm, hcur, rowptr, esrc, wg, woin);

        launch_gemm(woin, wo, hnext, NN, HID, WO_IN, 1);    // leaky_relu

        float* t = hcur; hcur = hnext; hnext = t;
    }

    // logits + log_softmax
    launch_gemm(hcur, w_out, logits, NN, NCLS, HID, 0);
    logsoftmax_k<<<(NN + 3) / 4, 128>>>(logits, out);
}